// round 8
// baseline (speedup 1.0000x reference)
#include <cuda_runtime.h>
#include <cstdint>

#define THREADS 512
#define NWARPS 16
#define RANK 8
#define K4 1024            // K/4
#define N4 1024            // N/4
#define MAXROWS 64
#define SLOTS 8            // smem ring slots (16KB each)
#define LORA_SCALE 2.0f    // alpha/r = 16/8

// ---- packed f32x2 helpers (FFMA2 only reachable via PTX) ----
__device__ __forceinline__ uint64_t pack2(float lo, float hi) {
    uint64_t r; asm("mov.b64 %0, {%1, %2};" : "=l"(r) : "f"(lo), "f"(hi)); return r;
}
__device__ __forceinline__ void unpack2(uint64_t v, float& lo, float& hi) {
    asm("mov.b64 {%0, %1}, %2;" : "=f"(lo), "=f"(hi) : "l"(v));
}
__device__ __forceinline__ uint64_t fma2(uint64_t a, uint64_t b, uint64_t c) {
    uint64_t d; asm("fma.rn.f32x2 %0, %1, %2, %3;" : "=l"(d) : "l"(a), "l"(b), "l"(c)); return d;
}

// ---- cp.async (LDGSTS) helpers ----
__device__ __forceinline__ void cp_async16(uint32_t dst_smem, const void* src) {
    asm volatile("cp.async.cg.shared.global [%0], [%1], 16;"
                 :: "r"(dst_smem), "l"(src) : "memory");
}
__device__ __forceinline__ void cp_commit() {
    asm volatile("cp.async.commit_group;" ::: "memory");
}
template <int N>
__device__ __forceinline__ void cp_wait() {
    asm volatile("cp.async.wait_group %0;" :: "n"(N) : "memory");
}

__global__ __launch_bounds__(THREADS, 1)
void lora_fused_kernel(const float4* __restrict__ x4,
                       const float4* __restrict__ A4,
                       const float4* __restrict__ B4,
                       float4* __restrict__ out4,
                       int rows, int grid)
{
    extern __shared__ char raw[];
    float4* s_x    = reinterpret_cast<float4*>(raw);                  // [SLOTS][1024] (128 KB)
    float*  s_part = reinterpret_cast<float*>(raw + SLOTS * K4 * 16); // [MAXROWS][NWARPS][8] (32 KB)
    float*  s_t    = s_part + MAXROWS * NWARPS * 8;                   // [MAXROWS][8]

    const int tid  = threadIdx.x;
    const int lane = tid & 31;
    const int warp = tid >> 5;

    const int r0 = (int)((long)blockIdx.x * rows / grid);
    const int r1 = (int)((long)(blockIdx.x + 1) * rows / grid);
    const int nr = r1 - r0;                    // ~53-54

    const int c0 = tid;
    const int c1 = tid + THREADS;

    const uint32_t sx = (uint32_t)__cvta_generic_to_shared(s_x);
    const uint32_t my_off = (uint32_t)tid * 16u;

    // ---------------- A cache: 2 chunks x 4 k x 4 j-pairs (64 regs) ----------
    uint64_t a2[2][4][4];
#pragma unroll
    for (int ch = 0; ch < 2; ch++) {
        const int c = ch ? c1 : c0;
#pragma unroll
        for (int kk = 0; kk < 4; kk++) {
            float4 lo = A4[c * 8 + kk * 2];
            float4 hi = A4[c * 8 + kk * 2 + 1];
            a2[ch][kk][0] = pack2(lo.x, lo.y);
            a2[ch][kk][1] = pack2(lo.z, lo.w);
            a2[ch][kk][2] = pack2(hi.x, hi.y);
            a2[ch][kk][3] = pack2(hi.z, hi.w);
        }
    }

    const int j_mine = ((lane >> 4) & 1) * 4 + ((lane >> 3) & 1) * 2 + ((lane >> 2) & 1);
    const bool write_lane = (lane & 3) == 0;
    const bool h  = (lane & 16) != 0;
    const bool qb = (lane & 8) != 0;
    const bool ob = (lane & 4) != 0;

    // ---------------- Prologue: stage rows 0..5 into the ring ----------------
#pragma unroll
    for (int d = 0; d < 6; d++) {
        int row = (d < nr) ? d : (nr - 1);
        const size_t xb = (size_t)(r0 + row) * K4;
        uint32_t dst = sx + (uint32_t)(d & (SLOTS - 1)) * (K4 * 16u) + my_off;
        cp_async16(dst,                 x4 + xb + c0);
        cp_async16(dst + THREADS * 16u, x4 + xb + c1);
        cp_commit();
    }

    // ---------------- Phase 1: 2 rows/iter, interleaved folding reduce --------
    for (int rb = 0; rb < nr; rb += 2) {
        cp_wait<4>();                      // rows rb, rb+1 complete

        const int sA = rb & (SLOTS - 1);
        const int sB = (rb + 1) & (SLOTS - 1);
        const float4 xa0 = s_x[sA * K4 + c0];
        const float4 xa1 = s_x[sA * K4 + c1];
        const float4 xb0 = s_x[sB * K4 + c0];  // stale if rb+1>=nr: result discarded
        const float4 xb1 = s_x[sB * K4 + c1];

        uint64_t pA2[4] = {0,0,0,0}, pB2[4] = {0,0,0,0};
        {
            const float fa[4] = {xa0.x, xa0.y, xa0.z, xa0.w};
            const float fb[4] = {xb0.x, xb0.y, xb0.z, xb0.w};
#pragma unroll
            for (int kk = 0; kk < 4; kk++) {
                uint64_t sa = pack2(fa[kk], fa[kk]);
                uint64_t sb = pack2(fb[kk], fb[kk]);
#pragma unroll
                for (int jp = 0; jp < 4; jp++) {
                    pA2[jp] = fma2(sa, a2[0][kk][jp], pA2[jp]);
                    pB2[jp] = fma2(sb, a2[0][kk][jp], pB2[jp]);
                }
            }
        }
        {
            const float fa[4] = {xa1.x, xa1.y, xa1.z, xa1.w};
            const float fb[4] = {xb1.x, xb1.y, xb1.z, xb1.w};
#pragma unroll
            for (int kk = 0; kk < 4; kk++) {
                uint64_t sa = pack2(fa[kk], fa[kk]);
                uint64_t sb = pack2(fb[kk], fb[kk]);
#pragma unroll
                for (int jp = 0; jp < 4; jp++) {
                    pA2[jp] = fma2(sa, a2[1][kk][jp], pA2[jp]);
                    pB2[jp] = fma2(sb, a2[1][kk][jp], pB2[jp]);
                }
            }
        }

        // Refill rows rb+6, rb+7; commit ALWAYS (empty groups keep invariant)
        {
            const int rrA = rb + 6;
            if (rrA < nr) {
                const size_t xbs = (size_t)(r0 + rrA) * K4;
                uint32_t dst = sx + (uint32_t)(rrA & (SLOTS - 1)) * (K4 * 16u) + my_off;
                cp_async16(dst,                 x4 + xbs + c0);
                cp_async16(dst + THREADS * 16u, x4 + xbs + c1);
            }
            cp_commit();
            const int rrB = rb + 7;
            if (rrB < nr) {
                const size_t xbs = (size_t)(r0 + rrB) * K4;
                uint32_t dst = sx + (uint32_t)(rrB & (SLOTS - 1)) * (K4 * 16u) + my_off;
                cp_async16(dst,                 x4 + xbs + c0);
                cp_async16(dst + THREADS * 16u, x4 + xbs + c1);
            }
            cp_commit();
        }

        // Two interleaved folding butterflies (independent chains overlap)
        float pA[8], pB[8];
#pragma unroll
        for (int jp = 0; jp < 4; jp++) {
            unpack2(pA2[jp], pA[2 * jp], pA[2 * jp + 1]);
            unpack2(pB2[jp], pB[2 * jp], pB[2 * jp + 1]);
        }

        float qA[4], qB[4];
#pragma unroll
        for (int m = 0; m < 4; m++) {
            float sendA = h ? pA[m] : pA[m + 4];
            float keepA = h ? pA[m + 4] : pA[m];
            float sendB = h ? pB[m] : pB[m + 4];
            float keepB = h ? pB[m + 4] : pB[m];
            qA[m] = keepA + __shfl_xor_sync(0xffffffffu, sendA, 16);
            qB[m] = keepB + __shfl_xor_sync(0xffffffffu, sendB, 16);
        }
        float uA[2], uB[2];
#pragma unroll
        for (int m = 0; m < 2; m++) {
            float sendA = qb ? qA[m] : qA[m + 2];
            float keepA = qb ? qA[m + 2] : qA[m];
            float sendB = qb ? qB[m] : qB[m + 2];
            float keepB = qb ? qB[m + 2] : qB[m];
            uA[m] = keepA + __shfl_xor_sync(0xffffffffu, sendA, 8);
            uB[m] = keepB + __shfl_xor_sync(0xffffffffu, sendB, 8);
        }
        float sendA = ob ? uA[0] : uA[1];
        float keepA = ob ? uA[1] : uA[0];
        float sendB = ob ? uB[0] : uB[1];
        float keepB = ob ? uB[1] : uB[0];
        float wA = keepA + __shfl_xor_sync(0xffffffffu, sendA, 4);
        float wB = keepB + __shfl_xor_sync(0xffffffffu, sendB, 4);
        wA += __shfl_xor_sync(0xffffffffu, wA, 2);
        wB += __shfl_xor_sync(0xffffffffu, wB, 2);
        wA += __shfl_xor_sync(0xffffffffu, wA, 1);
        wB += __shfl_xor_sync(0xffffffffu, wB, 1);

        if (write_lane) {
            s_part[rb * (NWARPS * 8) + warp * 8 + j_mine] = wA;
            if (rb + 1 < nr)
                s_part[(rb + 1) * (NWARPS * 8) + warp * 8 + j_mine] = wB;
        }
    }

    // ---------------- B cache (DRAM latency overlaps stragglers) -------------
    uint64_t b2[2][8][2];
#pragma unroll
    for (int ch = 0; ch < 2; ch++) {
        const int c = ch ? c1 : c0;
#pragma unroll
        for (int j = 0; j < RANK; j++) {
            float4 v = B4[j * N4 + c];
            v.x *= LORA_SCALE; v.y *= LORA_SCALE; v.z *= LORA_SCALE; v.w *= LORA_SCALE;
            b2[ch][j][0] = pack2(v.x, v.y);
            b2[ch][j][1] = pack2(v.z, v.w);
        }
    }

    __syncthreads();

    // ---------------- Cross-warp reduce into s_t ------------------------------
    for (int i = tid; i < nr * RANK; i += THREADS) {
        const int row = i >> 3, j = i & 7;
        float s = 0.0f;
#pragma unroll
        for (int w = 0; w < NWARPS; w++)
            s += s_part[row * (NWARPS * 8) + w * 8 + j];
        s_t[i] = s;
    }
    __syncthreads();

    // ---------------- Phase 2: out = t @ (B*scale), 2 rows/iter ---------------
    for (int rb = 0; rb < nr; rb += 2) {
        const int rA2 = rb;
        const int rB2 = (rb + 1 < nr) ? rb + 1 : rb;   // clamp (dup store harmless)

        float4 tA0 = *reinterpret_cast<const float4*>(&s_t[rA2 * RANK]);
        float4 tA1 = *reinterpret_cast<const float4*>(&s_t[rA2 * RANK + 4]);
        float4 tB0 = *reinterpret_cast<const float4*>(&s_t[rB2 * RANK]);
        float4 tB1 = *reinterpret_cast<const float4*>(&s_t[rB2 * RANK + 4]);

        uint64_t tsA[8], tsB[8];
        tsA[0] = pack2(tA0.x, tA0.x); tsA[1] = pack2(tA0.y, tA0.y);
        tsA[2] = pack2(tA0.z, tA0.z); tsA[3] = pack2(tA0.w, tA0.w);
        tsA[4] = pack2(tA1.x, tA1.x); tsA[5] = pack2(tA1.y, tA1.y);
        tsA[6] = pack2(tA1.z, tA1.z); tsA[7] = pack2(tA1.w, tA1.w);
        tsB[0] = pack2(tB0.x, tB0.x); tsB[1] = pack2(tB0.y, tB0.y);
        tsB[2] = pack2(tB0.z, tB0.z); tsB[3] = pack2(tB0.w, tB0.w);
        tsB[4] = pack2(tB1.x, tB1.x); tsB[5] = pack2(tB1.y, tB1.y);
        tsB[6] = pack2(tB1.z, tB1.z); tsB[7] = pack2(tB1.w, tB1.w);

        const size_t obA = (size_t)(r0 + rA2) * N4;
        const size_t obB = (size_t)(r0 + rB2) * N4;
#pragma unroll
        for (int ch = 0; ch < 2; ch++) {
            const int c = ch ? c1 : c0;
            uint64_t oA0 = 0, oA1 = 0, oB0 = 0, oB1 = 0;
#pragma unroll
            for (int j = 0; j < RANK; j++) {
                oA0 = fma2(tsA[j], b2[ch][j][0], oA0);
                oA1 = fma2(tsA[j], b2[ch][j][1], oA1);
                oB0 = fma2(tsB[j], b2[ch][j][0], oB0);
                oB1 = fma2(tsB[j], b2[ch][j][1], oB1);
            }
            float4 oA, oB;
            unpack2(oA0, oA.x, oA.y); unpack2(oA1, oA.z, oA.w);
            unpack2(oB0, oB.x, oB.y); unpack2(oB1, oB.z, oB.w);
            out4[obA + c] = oA;
            out4[obB + c] = oB;
        }
    }
}

extern "C" void kernel_launch(void* const* d_in, const int* in_sizes, int n_in,
                              void* d_out, int out_size)
{
    const float4* x4 = (const float4*)d_in[0];   // [4,2048,4096]
    const float4* A4 = (const float4*)d_in[1];   // [4096,8]
    const float4* B4 = (const float4*)d_in[2];   // [8,4096]
    float4* out4 = (float4*)d_out;

    const int K    = in_sizes[1] / RANK;         // 4096
    const int rows = in_sizes[0] / K;            // 8192

    int sms = 148;
    cudaDeviceGetAttribute(&sms, cudaDevAttrMultiProcessorCount, 0);

    const int smem = SLOTS * K4 * 16 +                           // x ring: 128 KB
                     MAXROWS * NWARPS * 8 * (int)sizeof(float) + // partials: 32 KB
                     MAXROWS * RANK * (int)sizeof(float);        // t: 2 KB
    cudaFuncSetAttribute(lora_fused_kernel,
                         cudaFuncAttributeMaxDynamicSharedMemorySize, smem);

    lora_fused_kernel<<<sms, THREADS, smem>>>(x4, A4, B4, out4, rows, sms);
}